// round 14
// baseline (speedup 1.0000x reference)
#include <cuda_runtime.h>
#include <math.h>
#include <stdint.h>

#define HEADS 12
#define DIM   64
#define BATCH 2
#define SEQ   2048
#define EMB   768
#define QKVN  (3 * HEADS * DIM)   // 2304
#define ROWS  (BATCH * SEQ)       // 4096
#define MASKN (BATCH * SEQ * SEQ) // 8388608

// ----- device scratch (all tf32-as-uint32) -----
__device__ uint32_t g_qtf[ROWS * EMB];
__device__ uint32_t g_ktf[ROWS * EMB];
__device__ uint32_t g_vtf[ROWS * EMB];
__device__ uint32_t g_xtf[ROWS * EMB];
__device__ uint32_t g_atttf[ROWS * EMB];
__device__ uint32_t g_wpretf[EMB * QKVN];
__device__ uint32_t g_wprojtf[EMB * EMB];
__device__ int   g_mask_allones;

// ============================ helpers =======================================
__device__ __forceinline__ uint32_t to_tf32(float x) {
    uint32_t r;
    asm("cvt.rna.tf32.f32 %0, %1;" : "=r"(r) : "f"(x));
    return r;
}
__device__ __forceinline__ void mma_tf32(float c[4],
                                         uint32_t a0, uint32_t a1, uint32_t a2, uint32_t a3,
                                         uint32_t b0, uint32_t b1) {
    asm volatile(
        "mma.sync.aligned.m16n8k8.row.col.f32.tf32.tf32.f32 "
        "{%0,%1,%2,%3}, {%4,%5,%6,%7}, {%8,%9}, {%0,%1,%2,%3};"
        : "+f"(c[0]), "+f"(c[1]), "+f"(c[2]), "+f"(c[3])
        : "r"(a0), "r"(a1), "r"(a2), "r"(a3), "r"(b0), "r"(b1));
}
#define CP16(dst, src) \
    asm volatile("cp.async.ca.shared.global [%0], [%1], 16;" :: "r"(dst), "l"(src) : "memory")
#define CP_COMMIT() asm volatile("cp.async.commit_group;" ::: "memory")
#define CP_WAIT1() asm volatile("cp.async.wait_group 1;" ::: "memory")
#define CP_WAIT0() asm volatile("cp.async.wait_group 0;" ::: "memory")

// ============================ fused prepass: fp32 -> tf32 (x, Wpre, Wproj) ==
#define XN4  (ROWS * EMB / 4)        // 786432
#define WPN4 (EMB * QKVN / 4)        // 442368
#define WJN4 (EMB * EMB / 4)         // 147456
#define TOTN4 (XN4 + WPN4 + WJN4)

__global__ void cvt_all_kernel(const float4* __restrict__ x,
                               const float4* __restrict__ wpre,
                               const float4* __restrict__ wproj,
                               uint4* __restrict__ xo,
                               uint4* __restrict__ wpo,
                               uint4* __restrict__ wjo) {
    for (int i = blockIdx.x * blockDim.x + threadIdx.x; i < TOTN4;
         i += gridDim.x * blockDim.x) {
        const float4* src;
        uint4* dst;
        int k;
        if (i < XN4) { src = x; dst = xo; k = i; }
        else if (i < XN4 + WPN4) { src = wpre; dst = wpo; k = i - XN4; }
        else { src = wproj; dst = wjo; k = i - XN4 - WPN4; }
        float4 v = src[k];
        dst[k] = make_uint4(to_tf32(v.x), to_tf32(v.y), to_tf32(v.z), to_tf32(v.w));
    }
}

// ============================ GEMM 128x128 tile (single tf32) ===============
#define G5_BYTES 71680

template <int MODE>
__global__ void __launch_bounds__(256, 2)
gemm_tf_kernel(const uint32_t* __restrict__ Atf, const uint32_t* __restrict__ Btf,
               const float* __restrict__ bias, float* __restrict__ C,
               uint32_t* __restrict__ qtf, uint32_t* __restrict__ ktf,
               uint32_t* __restrict__ vtf,
               int M, int N, int K) {
    extern __shared__ char smraw[];
    uint32_t* usm = reinterpret_cast<uint32_t*>(smraw);
    const uint32_t sb = (uint32_t)__cvta_generic_to_shared(smraw);

    const int tid = threadIdx.x;
    const int wid = tid >> 5;
    const int lane = tid & 31;
    const int g  = lane >> 2;
    const int tq = lane & 3;
    const int wm = wid >> 1;
    const int wn = wid & 1;
    const int m0 = blockIdx.y * 128;
    const int n0 = blockIdx.x * 128;
    const int nkt = K / 32;

    float acc[2][8][4];
#pragma unroll
    for (int i = 0; i < 2; i++)
#pragma unroll
        for (int j = 0; j < 8; j++)
#pragma unroll
            for (int r = 0; r < 4; r++) acc[i][j][r] = 0.0f;

    auto issue_tile = [&](int s, int kt) {
#pragma unroll
        for (int p = 0; p < 4; p++) {
            int idx = p * 256 + tid;
            int r = idx >> 3, ch = idx & 7;
            const uint32_t* src = Atf + (size_t)(m0 + r) * K + kt * 32 + ch * 4;
            uint32_t dst = sb + s * 18432 + (r * 36 + ch * 4) * 4;
            CP16(dst, src);
        }
#pragma unroll
        for (int p = 0; p < 4; p++) {
            int idx = p * 256 + tid;
            int r = idx >> 5, ch = idx & 31;
            const uint32_t* src = Btf + (size_t)(kt * 32 + r) * N + n0 + ch * 4;
            uint32_t dst = sb + 36864 + s * 17408 + (r * 136 + ch * 4) * 4;
            CP16(dst, src);
        }
        CP_COMMIT();
    };

    issue_tile(0, 0);

    for (int kt = 0; kt < nkt; kt++) {
        const int s = kt & 1;
        if (kt + 1 < nkt) {
            issue_tile(1 - s, kt + 1);
            CP_WAIT1();
        } else {
            CP_WAIT0();
        }
        __syncthreads();

        const uint32_t* sA = usm + s * 4608;
        const uint32_t* sB = usm + 9216 + s * 4352;

#pragma unroll
        for (int ks = 0; ks < 4; ks++) {
            const int kb = ks * 8;
            uint32_t af[2][4];
#pragma unroll
            for (int i = 0; i < 2; i++) {
                const int rbase = (wm * 32 + i * 16 + g) * 36 + kb + tq;
                af[i][0] = sA[rbase];
                af[i][1] = sA[rbase + 8 * 36];
                af[i][2] = sA[rbase + 4];
                af[i][3] = sA[rbase + 8 * 36 + 4];
            }
            uint32_t bf[8][2];
#pragma unroll
            for (int j = 0; j < 8; j++) {
                const int col = wn * 64 + j * 8 + g;
                bf[j][0] = sB[(kb + tq) * 136 + col];
                bf[j][1] = sB[(kb + tq + 4) * 136 + col];
            }
#pragma unroll
            for (int i = 0; i < 2; i++)
#pragma unroll
                for (int j = 0; j < 8; j++)
                    mma_tf32(acc[i][j], af[i][0], af[i][1], af[i][2], af[i][3],
                             bf[j][0], bf[j][1]);
        }
        __syncthreads();
    }

    const int region = n0 / EMB;
#pragma unroll
    for (int i = 0; i < 2; i++) {
        const int row = m0 + wm * 32 + i * 16 + g;
#pragma unroll
        for (int j = 0; j < 8; j++) {
            const int col = n0 + wn * 64 + j * 8 + 2 * tq;
            const float b0 = bias[col], b1 = bias[col + 1];
            float v00 = acc[i][j][0] + b0, v01 = acc[i][j][1] + b1;
            float v10 = acc[i][j][2] + b0, v11 = acc[i][j][3] + b1;
            if (MODE == 0) {
                *reinterpret_cast<float2*>(&C[(size_t)row * N + col]) =
                    make_float2(v00, v01);
                *reinterpret_cast<float2*>(&C[(size_t)(row + 8) * N + col]) =
                    make_float2(v10, v11);
            } else {
                const int cemb = col - region * EMB;
                const size_t a0 = (size_t)row * EMB + cemb;
                const size_t a1 = (size_t)(row + 8) * EMB + cemb;
                uint32_t* dst = (region == 0) ? qtf : (region == 1) ? ktf : vtf;
                const float sc = (region == 0) ? 0.125f : 1.0f;
                *reinterpret_cast<uint2*>(&dst[a0]) =
                    make_uint2(to_tf32(sc * v00), to_tf32(sc * v01));
                *reinterpret_cast<uint2*>(&dst[a1]) =
                    make_uint2(to_tf32(sc * v10), to_tf32(sc * v11));
            }
        }
    }
}

// ============================ mask scan (detect fused) ======================
__device__ __forceinline__ unsigned int haszero_byte(unsigned int v) {
    return (v - 0x01010101u) & ~v & 0x80808080u;
}

__global__ void mask_scan_kernel(const uint4* __restrict__ mask) {
    if (blockIdx.x == 0 && threadIdx.x == 0) g_mask_allones = 1;
    // element size detection from word 0 (true-encodings: u8 0x01010101,
    // i32 1, f32 0x3f800000)
    unsigned int w0 = ((const unsigned int*)mask)[0];
    bool esize4 = !(w0 == 0x01010101u ||
                    ((w0 & 0xFFu) != 0u && (w0 != 1u && w0 != 0x3f800000u) &&
                     (w0 >> 8) == 0u) ? false : (w0 == 1u || w0 == 0x3f800000u));
    // simpler: esize==1 iff w0==0x01010101 or (low byte nonzero and high bytes nonzero)
    bool e1 = (w0 == 0x01010101u);
    bool e4 = (w0 == 1u || w0 == 0x3f800000u);
    if (!e1 && !e4) e1 = ((w0 & 0xFFu) != 0u || (w0 >> 8) == 0u);
    unsigned int any = 0;
    if (!e1) {
        const int n = MASKN / 4;
        for (int i = blockIdx.x * blockDim.x + threadIdx.x; i < n;
             i += gridDim.x * blockDim.x) {
            uint4 w = mask[i];
            any |= (w.x == 0u) | (w.y == 0u) | (w.z == 0u) | (w.w == 0u);
        }
    } else {
        const int n = MASKN / 16;
        for (int i = blockIdx.x * blockDim.x + threadIdx.x; i < n;
             i += gridDim.x * blockDim.x) {
            uint4 w = mask[i];
            any |= haszero_byte(w.x) | haszero_byte(w.y) |
                   haszero_byte(w.z) | haszero_byte(w.w);
        }
    }
    if (any) g_mask_allones = 0;
    (void)esize4;
}

// Mask esize re-detected inside attention (cheap, L2-hit read of word 0).

// ============================ attention: 64-q tiles, warp key-split =========
// 256 threads (8 warps). Warp w: rows (w>>1)*16..+15, key-half (w&1)*32 of
// each 64-key chunk. Independent online softmax per warp; exact in-CTA
// combine of warp pairs at the end (flash split-K identity).
// smem: stage s: K @ s*9216 [64][68]; V @ s*9216+4352 [64][76] (floats).
// Q staged at 9216 (64x68). End combine reuses sh[0..8960).
#define AT5_BYTES (18432 * 4)

__global__ void __launch_bounds__(256, 2)
attn_mma_kernel(const uint32_t* __restrict__ qtf, const uint32_t* __restrict__ ktf,
                const uint32_t* __restrict__ vtf,
                const void* __restrict__ mask,
                uint32_t* __restrict__ atttf) {
    extern __shared__ float sh[];
    const uint32_t sb = (uint32_t)__cvta_generic_to_shared(sh);

    const int tid = threadIdx.x;
    const int wid = tid >> 5;
    const int lane = tid & 31;
    const int g  = lane >> 2;
    const int tq = lane & 3;
    const int wq = (wid >> 1) * 16;     // row group (4 groups of 16)
    const int kh = (wid & 1) * 32;      // key half within chunk
    const int q0 = blockIdx.x * 64;
    const int h  = blockIdx.y;
    const int b  = blockIdx.z;

    const int mask_allones = g_mask_allones;
    const size_t rbase = (size_t)b * SEQ;
    const int hoff = h * DIM;
    const size_t mask_base = (size_t)b * SEQ * SEQ;

    // mask element size (only needed on slow path)
    int mask_esize = 4;
    {
        unsigned int w0 = ((const unsigned int*)mask)[0];
        if (w0 == 0x01010101u) mask_esize = 1;
        else if (w0 == 1u || w0 == 0x3f800000u) mask_esize = 4;
        else if ((w0 & 0xFFu) != 0u || (w0 >> 8) == 0u) mask_esize = 1;
    }

    auto issue_kv = [&](int s, int kt) {
        const int k0 = kt * 64;
#pragma unroll
        for (int p = 0; p < 4; p++) {
            int idx = p * 256 + tid;
            int key = idx >> 4, c = idx & 15;
            const uint32_t* src = ktf + (rbase + k0 + key) * EMB + hoff + c * 4;
            uint32_t dst = sb + (s * 9216 + key * 68 + c * 4) * 4;
            CP16(dst, src);
        }
#pragma unroll
        for (int p = 0; p < 4; p++) {
            int idx = p * 256 + tid;
            int key = idx >> 4, c = idx & 15;
            const uint32_t* src = vtf + (rbase + k0 + key) * EMB + hoff + c * 4;
            uint32_t dst = sb + (s * 9216 + 4352 + key * 76 + c * 4) * 4;
            CP16(dst, src);
        }
        CP_COMMIT();
    };

    // ---- stage Q (64 rows) into stage-1 region ----
#pragma unroll
    for (int p = 0; p < 4; p++) {
        int idx = p * 256 + tid;
        int r = idx >> 4, c = idx & 15;
        const uint32_t* src = qtf + (rbase + q0 + r) * EMB + hoff + c * 4;
        uint32_t dst = sb + (9216 + r * 68 + c * 4) * 4;
        CP16(dst, src);
    }
    CP_COMMIT();
    CP_WAIT0();
    __syncthreads();

    const uint32_t* Qstage = reinterpret_cast<const uint32_t*>(sh + 9216);
    uint32_t qf[8][4];
#pragma unroll
    for (int kb = 0; kb < 8; kb++) {
        const int r0 = (wq + g) * 68 + kb * 8 + tq;
        const int r1 = (wq + g + 8) * 68 + kb * 8 + tq;
        qf[kb][0] = Qstage[r0];
        qf[kb][1] = Qstage[r1];
        qf[kb][2] = Qstage[r0 + 4];
        qf[kb][3] = Qstage[r1 + 4];
    }
    __syncthreads();
    issue_kv(0, 0);

    float o[8][4];
#pragma unroll
    for (int nt = 0; nt < 8; nt++)
#pragma unroll
        for (int r = 0; r < 4; r++) o[nt][r] = 0.0f;
    float m0r = -1e30f, m1r = -1e30f, l0r = 0.0f, l1r = 0.0f;

    const int nkt = SEQ / 64;
    for (int kt = 0; kt < nkt; kt++) {
        const int s = kt & 1;
        const int k0 = kt * 64;
        if (kt + 1 < nkt) {
            issue_kv(1 - s, kt + 1);
            CP_WAIT1();
        } else {
            CP_WAIT0();
        }
        __syncthreads();

        const uint32_t* Ktf_s = reinterpret_cast<const uint32_t*>(sh + s * 9216);
        const uint32_t* Vtf_s = reinterpret_cast<const uint32_t*>(sh + s * 9216 + 4352);

        // ---- S = (Q/8) K^T over this warp's 32 keys ----
        float s4[4][4];
#pragma unroll
        for (int nt = 0; nt < 4; nt++)
#pragma unroll
            for (int r = 0; r < 4; r++) s4[nt][r] = 0.0f;
#pragma unroll
        for (int kb = 0; kb < 8; kb++) {
#pragma unroll
            for (int nt = 0; nt < 4; nt++) {
                const int col = kh + nt * 8 + g;
                uint32_t b0 = Ktf_s[col * 68 + kb * 8 + tq];
                uint32_t b1 = Ktf_s[col * 68 + kb * 8 + tq + 4];
                mma_tf32(s4[nt], qf[kb][0], qf[kb][1], qf[kb][2], qf[kb][3], b0, b1);
            }
        }

        // ---- mask ----
        if (!mask_allones) {
            const int qg0 = q0 + wq + g, qg1 = qg0 + 8;
#pragma unroll
            for (int nt = 0; nt < 4; nt++) {
                int kcol = k0 + kh + nt * 8 + 2 * tq;
                bool mk[4];
                if (mask_esize == 4) {
                    const unsigned int* mm = (const unsigned int*)mask;
                    mk[0] = mm[mask_base + (size_t)qg0 * SEQ + kcol] != 0;
                    mk[1] = mm[mask_base + (size_t)qg0 * SEQ + kcol + 1] != 0;
                    mk[2] = mm[mask_base + (size_t)qg1 * SEQ + kcol] != 0;
                    mk[3] = mm[mask_base + (size_t)qg1 * SEQ + kcol + 1] != 0;
                } else {
                    const unsigned char* mm = (const unsigned char*)mask;
                    mk[0] = mm[mask_base + (size_t)qg0 * SEQ + kcol] != 0;
                    mk[1] = mm[mask_base + (size_t)qg0 * SEQ + kcol + 1] != 0;
                    mk[2] = mm[mask_base + (size_t)qg1 * SEQ + kcol] != 0;
                    mk[3] = mm[mask_base + (size_t)qg1 * SEQ + kcol + 1] != 0;
                }
#pragma unroll
                for (int r = 0; r < 4; r++)
                    if (!mk[r]) s4[nt][r] = -1e9f;
            }
        }

        // ---- online softmax (per-warp, over its 32 keys) ----
        float mt0 = -1e30f, mt1 = -1e30f;
#pragma unroll
        for (int nt = 0; nt < 4; nt++) {
            mt0 = fmaxf(mt0, fmaxf(s4[nt][0], s4[nt][1]));
            mt1 = fmaxf(mt1, fmaxf(s4[nt][2], s4[nt][3]));
        }
        mt0 = fmaxf(mt0, __shfl_xor_sync(0xffffffff, mt0, 1));
        mt0 = fmaxf(mt0, __shfl_xor_sync(0xffffffff, mt0, 2));
        mt1 = fmaxf(mt1, __shfl_xor_sync(0xffffffff, mt1, 1));
        mt1 = fmaxf(mt1, __shfl_xor_sync(0xffffffff, mt1, 2));

        float mn0 = fmaxf(m0r, mt0), mn1 = fmaxf(m1r, mt1);
        float a0 = __expf(m0r - mn0), a1 = __expf(m1r - mn1);
        m0r = mn0; m1r = mn1;

        float lt0 = 0.0f, lt1 = 0.0f;
#pragma unroll
        for (int nt = 0; nt < 4; nt++) {
            s4[nt][0] = __expf(s4[nt][0] - mn0);
            s4[nt][1] = __expf(s4[nt][1] - mn0);
            s4[nt][2] = __expf(s4[nt][2] - mn1);
            s4[nt][3] = __expf(s4[nt][3] - mn1);
            lt0 += s4[nt][0] + s4[nt][1];
            lt1 += s4[nt][2] + s4[nt][3];
        }
        lt0 += __shfl_xor_sync(0xffffffff, lt0, 1);
        lt0 += __shfl_xor_sync(0xffffffff, lt0, 2);
        lt1 += __shfl_xor_sync(0xffffffff, lt1, 1);
        lt1 += __shfl_xor_sync(0xffffffff, lt1, 2);
        l0r = l0r * a0 + lt0;
        l1r = l1r * a1 + lt1;

#pragma unroll
        for (int nt = 0; nt < 8; nt++) {
            o[nt][0] *= a0; o[nt][1] *= a0;
            o[nt][2] *= a1; o[nt][3] *= a1;
        }

        // ---- O += P @ V (P in registers, permuted-key trick; this warp's
        //      32 keys live at chunk offset kh) ----
#pragma unroll
        for (int kb = 0; kb < 4; kb++) {
            uint32_t pa0 = to_tf32(s4[kb][0]);
            uint32_t pa1 = to_tf32(s4[kb][2]);
            uint32_t pa2 = to_tf32(s4[kb][1]);
            uint32_t pa3 = to_tf32(s4[kb][3]);
            const int vr0 = (kh + kb * 8 + 2 * tq) * 76;
            const int vr1 = (kh + kb * 8 + 2 * tq + 1) * 76;
#pragma unroll
            for (int nt = 0; nt < 8; nt++) {
                const int d = nt * 8 + g;
                mma_tf32(o[nt], pa0, pa1, pa2, pa3,
                         Vtf_s[vr0 + d], Vtf_s[vr1 + d]);
            }
        }
        __syncthreads();
    }

    // ---- exact warp-pair combine in smem ----
    // o_sm: warp w region @ w*1088 : [16 rows][68 stride]; ml @ 8704+w*64.
    uint32_t* o_sm = reinterpret_cast<uint32_t*>(sh);
    float* ml_sm = sh + 8704;
#pragma unroll
    for (int nt = 0; nt < 8; nt++) {
        const int base0 = wid * 1088 + g * 68 + nt * 8 + 2 * tq;
        const int base1 = wid * 1088 + (g + 8) * 68 + nt * 8 + 2 * tq;
        o_sm[base0] = __float_as_uint(o[nt][0]);
        o_sm[base0 + 1] = __float_as_uint(o[nt][1]);
        o_sm[base1] = __float_as_uint(o[nt][2]);
        o_sm[base1 + 1] = __float_as_uint(o[nt][3]);
    }
    if (tq == 0) {
        ml_sm[wid * 64 + g * 2] = m0r;
        ml_sm[wid * 64 + g * 2 + 1] = l0r;
        ml_sm[wid * 64 + (g + 8) * 2] = m1r;
        ml_sm[wid * 64 + (g + 8) * 2 + 1] = l1r;
    }
    __syncthreads();

    if ((wid & 1) == 0) {
        const int ow = wid + 1;
        float mo0 = ml_sm[ow * 64 + g * 2];
        float lo0 = ml_sm[ow * 64 + g * 2 + 1];
        float mo1 = ml_sm[ow * 64 + (g + 8) * 2];
        float lo1 = ml_sm[ow * 64 + (g + 8) * 2 + 1];

        float M0 = fmaxf(m0r, mo0), M1 = fmaxf(m1r, mo1);
        float ae0 = __expf(m0r - M0), ao0 = __expf(mo0 - M0);
        float ae1 = __expf(m1r - M1), ao1 = __expf(mo1 - M1);
        float inv0 = 1.0f / (ae0 * l0r + ao0 * lo0);
        float inv1 = 1.0f / (ae1 * l1r + ao1 * lo1);

        const size_t row0 = rbase + q0 + wq + g;
        const size_t row1 = row0 + 8;
#pragma unroll
        for (int nt = 0; nt < 8; nt++) {
            const int c2 = nt * 8 + 2 * tq;
            float oo0 = __uint_as_float(o_sm[ow * 1088 + g * 68 + c2]);
            float oo1 = __uint_as_float(o_sm[ow * 1088 + g * 68 + c2 + 1]);
            float oo2 = __uint_as_float(o_sm[ow * 1088 + (g + 8) * 68 + c2]);
            float oo3 = __uint_as_float(o_sm[ow * 1088 + (g + 8) * 68 + c2 + 1]);
            float f0 = (ae0 * o[nt][0] + ao0 * oo0) * inv0;
            float f1 = (ae0 * o[nt][1] + ao0 * oo1) * inv0;
            float f2 = (ae1 * o[nt][2] + ao1 * oo2) * inv1;
            float f3 = (ae1 * o[nt][3] + ao1 * oo3) * inv1;
            const int col = hoff + c2;
            *reinterpret_cast<uint2*>(&atttf[row0 * EMB + col]) =
                make_uint2(to_tf32(f0), to_tf32(f1));
            *reinterpret_cast<uint2*>(&atttf[row1 * EMB + col]) =
                make_uint2(to_tf32(f2), to_tf32(f3));
        }
    }
}

// ============================================================================
extern "C" void kernel_launch(void* const* d_in, const int* in_sizes, int n_in,
                              void* d_out, int out_size) {
    const float* x      = (const float*)d_in[0];
    const void*  mask   = d_in[1];
    const float* W_pre  = (const float*)d_in[2];
    const float* b_pre  = (const float*)d_in[3];
    const float* W_proj = (const float*)d_in[4];
    const float* b_proj = (const float*)d_in[5];
    float* out = (float*)d_out;

    uint32_t *qtf, *ktf, *vtf, *xtf, *atttf, *wpretf, *wprojtf;
    cudaGetSymbolAddress((void**)&qtf, g_qtf);
    cudaGetSymbolAddress((void**)&ktf, g_ktf);
    cudaGetSymbolAddress((void**)&vtf, g_vtf);
    cudaGetSymbolAddress((void**)&xtf, g_xtf);
    cudaGetSymbolAddress((void**)&atttf, g_atttf);
    cudaGetSymbolAddress((void**)&wpretf, g_wpretf);
    cudaGetSymbolAddress((void**)&wprojtf, g_wprojtf);

    mask_scan_kernel<<<512, 256>>>((const uint4*)mask);
    cvt_all_kernel<<<2048, 256>>>((const float4*)x, (const float4*)W_pre,
                                  (const float4*)W_proj,
                                  (uint4*)xtf, (uint4*)wpretf, (uint4*)wprojtf);

    cudaFuncSetAttribute(gemm_tf_kernel<0>,
                         cudaFuncAttributeMaxDynamicSharedMemorySize, G5_BYTES);
    cudaFuncSetAttribute(gemm_tf_kernel<1>,
                         cudaFuncAttributeMaxDynamicSharedMemorySize, G5_BYTES);
    cudaFuncSetAttribute(attn_mma_kernel,
                         cudaFuncAttributeMaxDynamicSharedMemorySize, AT5_BYTES);

    // 1) QKV GEMM -> attention-ready operands
    {
        dim3 grid(QKVN / 128, ROWS / 128);
        gemm_tf_kernel<1><<<grid, 256, G5_BYTES>>>(
            xtf, wpretf, b_pre, nullptr, qtf, ktf, vtf, ROWS, QKVN, EMB);
    }
    // 2) Attention (64-q tiles, warp key-split, exact in-CTA combine)
    {
        dim3 grid(SEQ / 64, HEADS, BATCH);
        attn_mma_kernel<<<grid, 256, AT5_BYTES>>>(qtf, ktf, vtf, mask, atttf);
    }
    // 3) Projection GEMM
    {
        dim3 grid(EMB / 128, ROWS / 128);
        gemm_tf_kernel<0><<<grid, 256, G5_BYTES>>>(
            atttf, wprojtf, b_proj, out, nullptr, nullptr, nullptr,
            ROWS, EMB, EMB);
    }
}

// round 15
// speedup vs baseline: 1.1069x; 1.1069x over previous
#include <cuda_runtime.h>
#include <math.h>
#include <stdint.h>

#define HEADS 12
#define DIM   64
#define BATCH 2
#define SEQ   2048
#define EMB   768
#define QKVN  (3 * HEADS * DIM)   // 2304
#define ROWS  (BATCH * SEQ)       // 4096
#define MASKN (BATCH * SEQ * SEQ) // 8388608

// ----- device scratch (all tf32-as-uint32) -----
__device__ uint32_t g_qtf[ROWS * EMB];
__device__ uint32_t g_ktf[ROWS * EMB];
__device__ uint32_t g_vtf[ROWS * EMB];
__device__ uint32_t g_xtf[ROWS * EMB];
__device__ uint32_t g_atttf[ROWS * EMB];
__device__ uint32_t g_wpretf[EMB * QKVN];
__device__ uint32_t g_wprojtf[EMB * EMB];
__device__ int   g_mask_esize;
__device__ int   g_mask_allones;

// ============================ helpers =======================================
__device__ __forceinline__ uint32_t to_tf32(float x) {
    uint32_t r;
    asm("cvt.rna.tf32.f32 %0, %1;" : "=r"(r) : "f"(x));
    return r;
}
__device__ __forceinline__ void mma_tf32(float c[4],
                                         uint32_t a0, uint32_t a1, uint32_t a2, uint32_t a3,
                                         uint32_t b0, uint32_t b1) {
    asm volatile(
        "mma.sync.aligned.m16n8k8.row.col.f32.tf32.tf32.f32 "
        "{%0,%1,%2,%3}, {%4,%5,%6,%7}, {%8,%9}, {%0,%1,%2,%3};"
        : "+f"(c[0]), "+f"(c[1]), "+f"(c[2]), "+f"(c[3])
        : "r"(a0), "r"(a1), "r"(a2), "r"(a3), "r"(b0), "r"(b1));
}
#define CP16(dst, src) \
    asm volatile("cp.async.cg.shared.global [%0], [%1], 16;" :: "r"(dst), "l"(src) : "memory")
#define CP_COMMIT() asm volatile("cp.async.commit_group;" ::: "memory")
#define CP_WAIT1() asm volatile("cp.async.wait_group 1;" ::: "memory")
#define CP_WAIT0() asm volatile("cp.async.wait_group 0;" ::: "memory")

// ============================ fused prepass: fp32 -> tf32 ===================
#define XN4  (ROWS * EMB / 4)
#define WPN4 (EMB * QKVN / 4)
#define WJN4 (EMB * EMB / 4)
#define TOTN4 (XN4 + WPN4 + WJN4)

__global__ void cvt_all_kernel(const float4* __restrict__ x,
                               const float4* __restrict__ wpre,
                               const float4* __restrict__ wproj,
                               uint4* __restrict__ xo,
                               uint4* __restrict__ wpo,
                               uint4* __restrict__ wjo) {
    for (int i = blockIdx.x * blockDim.x + threadIdx.x; i < TOTN4;
         i += gridDim.x * blockDim.x) {
        const float4* src;
        uint4* dst;
        int k;
        if (i < XN4) { src = x; dst = xo; k = i; }
        else if (i < XN4 + WPN4) { src = wpre; dst = wpo; k = i - XN4; }
        else { src = wproj; dst = wjo; k = i - XN4 - WPN4; }
        float4 v = src[k];
        dst[k] = make_uint4(to_tf32(v.x), to_tf32(v.y), to_tf32(v.z), to_tf32(v.w));
    }
}

// ============================ GEMM 128x128 tile (single tf32) ===============
#define G5_BYTES 71680

template <int MODE>
__global__ void __launch_bounds__(256, 2)
gemm_tf_kernel(const uint32_t* __restrict__ Atf, const uint32_t* __restrict__ Btf,
               const float* __restrict__ bias, float* __restrict__ C,
               uint32_t* __restrict__ qtf, uint32_t* __restrict__ ktf,
               uint32_t* __restrict__ vtf,
               int M, int N, int K) {
    extern __shared__ char smraw[];
    uint32_t* usm = reinterpret_cast<uint32_t*>(smraw);
    const uint32_t sb = (uint32_t)__cvta_generic_to_shared(smraw);

    const int tid = threadIdx.x;
    const int wid = tid >> 5;
    const int lane = tid & 31;
    const int g  = lane >> 2;
    const int tq = lane & 3;
    const int wm = wid >> 1;
    const int wn = wid & 1;
    const int m0 = blockIdx.y * 128;
    const int n0 = blockIdx.x * 128;
    const int nkt = K / 32;

    float acc[2][8][4];
#pragma unroll
    for (int i = 0; i < 2; i++)
#pragma unroll
        for (int j = 0; j < 8; j++)
#pragma unroll
            for (int r = 0; r < 4; r++) acc[i][j][r] = 0.0f;

    auto issue_tile = [&](int s, int kt) {
#pragma unroll
        for (int p = 0; p < 4; p++) {
            int idx = p * 256 + tid;
            int r = idx >> 3, ch = idx & 7;
            const uint32_t* src = Atf + (size_t)(m0 + r) * K + kt * 32 + ch * 4;
            uint32_t dst = sb + s * 18432 + (r * 36 + ch * 4) * 4;
            CP16(dst, src);
        }
#pragma unroll
        for (int p = 0; p < 4; p++) {
            int idx = p * 256 + tid;
            int r = idx >> 5, ch = idx & 31;
            const uint32_t* src = Btf + (size_t)(kt * 32 + r) * N + n0 + ch * 4;
            uint32_t dst = sb + 36864 + s * 17408 + (r * 136 + ch * 4) * 4;
            CP16(dst, src);
        }
        CP_COMMIT();
    };

    issue_tile(0, 0);

    for (int kt = 0; kt < nkt; kt++) {
        const int s = kt & 1;
        if (kt + 1 < nkt) {
            issue_tile(1 - s, kt + 1);
            CP_WAIT1();
        } else {
            CP_WAIT0();
        }
        __syncthreads();

        const uint32_t* sA = usm + s * 4608;
        const uint32_t* sB = usm + 9216 + s * 4352;

#pragma unroll
        for (int ks = 0; ks < 4; ks++) {
            const int kb = ks * 8;
            uint32_t af[2][4];
#pragma unroll
            for (int i = 0; i < 2; i++) {
                const int rbase = (wm * 32 + i * 16 + g) * 36 + kb + tq;
                af[i][0] = sA[rbase];
                af[i][1] = sA[rbase + 8 * 36];
                af[i][2] = sA[rbase + 4];
                af[i][3] = sA[rbase + 8 * 36 + 4];
            }
            uint32_t bf[8][2];
#pragma unroll
            for (int j = 0; j < 8; j++) {
                const int col = wn * 64 + j * 8 + g;
                bf[j][0] = sB[(kb + tq) * 136 + col];
                bf[j][1] = sB[(kb + tq + 4) * 136 + col];
            }
#pragma unroll
            for (int i = 0; i < 2; i++)
#pragma unroll
                for (int j = 0; j < 8; j++)
                    mma_tf32(acc[i][j], af[i][0], af[i][1], af[i][2], af[i][3],
                             bf[j][0], bf[j][1]);
        }
        __syncthreads();
    }

    const int region = n0 / EMB;
#pragma unroll
    for (int i = 0; i < 2; i++) {
        const int row = m0 + wm * 32 + i * 16 + g;
#pragma unroll
        for (int j = 0; j < 8; j++) {
            const int col = n0 + wn * 64 + j * 8 + 2 * tq;
            const float b0 = bias[col], b1 = bias[col + 1];
            float v00 = acc[i][j][0] + b0, v01 = acc[i][j][1] + b1;
            float v10 = acc[i][j][2] + b0, v11 = acc[i][j][3] + b1;
            if (MODE == 0) {
                *reinterpret_cast<float2*>(&C[(size_t)row * N + col]) =
                    make_float2(v00, v01);
                *reinterpret_cast<float2*>(&C[(size_t)(row + 8) * N + col]) =
                    make_float2(v10, v11);
            } else {
                const int cemb = col - region * EMB;
                const size_t a0 = (size_t)row * EMB + cemb;
                const size_t a1 = (size_t)(row + 8) * EMB + cemb;
                uint32_t* dst = (region == 0) ? qtf : (region == 1) ? ktf : vtf;
                const float sc = (region == 0) ? 0.125f : 1.0f;
                *reinterpret_cast<uint2*>(&dst[a0]) =
                    make_uint2(to_tf32(sc * v00), to_tf32(sc * v01));
                *reinterpret_cast<uint2*>(&dst[a1]) =
                    make_uint2(to_tf32(sc * v10), to_tf32(sc * v11));
            }
        }
    }
}

// ============================ mask scan (detect fused) ======================
__device__ __forceinline__ unsigned int haszero_byte(unsigned int v) {
    return (v - 0x01010101u) & ~v & 0x80808080u;
}

__global__ void mask_scan_kernel(const uint4* __restrict__ mask) {
    unsigned int w0 = ((const unsigned int*)mask)[0];
    int esize;
    if (w0 == 0x01010101u) esize = 1;
    else if (w0 == 1u || w0 == 0x3f800000u) esize = 4;
    else if ((w0 & 0xFFu) != 0u || (w0 >> 8) == 0u) esize = 1;
    else esize = 4;
    if (blockIdx.x == 0 && threadIdx.x == 0) {
        g_mask_esize = esize;
        g_mask_allones = 1;
    }
    unsigned int any = 0;
    if (esize == 4) {
        const int n = MASKN / 4;
        for (int i = blockIdx.x * blockDim.x + threadIdx.x; i < n;
             i += gridDim.x * blockDim.x) {
            uint4 w = mask[i];
            any |= (w.x == 0u) | (w.y == 0u) | (w.z == 0u) | (w.w == 0u);
        }
    } else {
        const int n = MASKN / 16;
        for (int i = blockIdx.x * blockDim.x + threadIdx.x; i < n;
             i += gridDim.x * blockDim.x) {
            uint4 w = mask[i];
            any |= haszero_byte(w.x) | haszero_byte(w.y) |
                   haszero_byte(w.z) | haszero_byte(w.w);
        }
    }
    if (any) g_mask_allones = 0;
}

// ============================ attention (R12 winner, cg loads) ==============
// 256 threads (8 warps), 128 query rows, chunks of 64 keys, double-buffered
// cp.async K/V. All operands single tf32. P register-resident via permuted-key
// PV (k-pos tq -> key 2tq, k-pos tq+4 -> key 2tq+1).
// smem floats per stage s: K @ s*9216 [64][68]; V @ s*9216+4352 [64][76].
#define AT4_BYTES (18432 * 4)

__global__ void __launch_bounds__(256, 2)
attn_mma_kernel(const uint32_t* __restrict__ qtf, const uint32_t* __restrict__ ktf,
                const uint32_t* __restrict__ vtf,
                const void* __restrict__ mask,
                uint32_t* __restrict__ atttf) {
    extern __shared__ float sh[];
    const uint32_t sb = (uint32_t)__cvta_generic_to_shared(sh);

    const int tid = threadIdx.x;
    const int wid = tid >> 5;
    const int lane = tid & 31;
    const int g  = lane >> 2;
    const int tq = lane & 3;
    const int wq = wid * 16;
    const int q0 = blockIdx.x * 128;
    const int h  = blockIdx.y;
    const int b  = blockIdx.z;

    const int mask_allones = g_mask_allones;
    const int mask_esize   = g_mask_esize;
    const size_t rbase = (size_t)b * SEQ;
    const int hoff = h * DIM;
    const size_t mask_base = (size_t)b * SEQ * SEQ;

    auto issue_kv = [&](int s, int kt) {
        const int k0 = kt * 64;
#pragma unroll
        for (int p = 0; p < 4; p++) {
            int idx = p * 256 + tid;
            int key = idx >> 4, c = idx & 15;
            const uint32_t* src = ktf + (rbase + k0 + key) * EMB + hoff + c * 4;
            uint32_t dst = sb + (s * 9216 + key * 68 + c * 4) * 4;
            CP16(dst, src);
        }
#pragma unroll
        for (int p = 0; p < 4; p++) {
            int idx = p * 256 + tid;
            int key = idx >> 4, c = idx & 15;
            const uint32_t* src = vtf + (rbase + k0 + key) * EMB + hoff + c * 4;
            uint32_t dst = sb + (s * 9216 + 4352 + key * 76 + c * 4) * 4;
            CP16(dst, src);
        }
        CP_COMMIT();
    };

#pragma unroll
    for (int p = 0; p < 8; p++) {
        int idx = p * 256 + tid;
        int r = idx >> 4, c = idx & 15;
        const uint32_t* src = qtf + (rbase + q0 + r) * EMB + hoff + c * 4;
        uint32_t dst = sb + (9216 + r * 68 + c * 4) * 4;
        CP16(dst, src);
    }
    CP_COMMIT();
    CP_WAIT0();
    __syncthreads();

    const uint32_t* Qstage = reinterpret_cast<const uint32_t*>(sh + 9216);
    uint32_t qf[8][4];
#pragma unroll
    for (int kb = 0; kb < 8; kb++) {
        const int r0 = (wq + g) * 68 + kb * 8 + tq;
        const int r1 = (wq + g + 8) * 68 + kb * 8 + tq;
        qf[kb][0] = Qstage[r0];
        qf[kb][1] = Qstage[r1];
        qf[kb][2] = Qstage[r0 + 4];
        qf[kb][3] = Qstage[r1 + 4];
    }
    __syncthreads();
    issue_kv(0, 0);

    float o[8][4];
#pragma unroll
    for (int nt = 0; nt < 8; nt++)
#pragma unroll
        for (int r = 0; r < 4; r++) o[nt][r] = 0.0f;
    float m0r = -1e30f, m1r = -1e30f, l0r = 0.0f, l1r = 0.0f;

    const int nkt = SEQ / 64;
    for (int kt = 0; kt < nkt; kt++) {
        const int s = kt & 1;
        const int k0 = kt * 64;
        if (kt + 1 < nkt) {
            issue_kv(1 - s, kt + 1);
            CP_WAIT1();
        } else {
            CP_WAIT0();
        }
        __syncthreads();

        const uint32_t* Ktf_s = reinterpret_cast<const uint32_t*>(sh + s * 9216);
        const uint32_t* Vtf_s = reinterpret_cast<const uint32_t*>(sh + s * 9216 + 4352);

        float s4[8][4];
#pragma unroll
        for (int nt = 0; nt < 8; nt++)
#pragma unroll
            for (int r = 0; r < 4; r++) s4[nt][r] = 0.0f;
#pragma unroll
        for (int kb = 0; kb < 8; kb++) {
#pragma unroll
            for (int nt = 0; nt < 8; nt++) {
                uint32_t b0 = Ktf_s[(nt * 8 + g) * 68 + kb * 8 + tq];
                uint32_t b1 = Ktf_s[(nt * 8 + g) * 68 + kb * 8 + tq + 4];
                mma_tf32(s4[nt], qf[kb][0], qf[kb][1], qf[kb][2], qf[kb][3], b0, b1);
            }
        }

        if (!mask_allones) {
            const int qg0 = q0 + wq + g, qg1 = qg0 + 8;
#pragma unroll
            for (int nt = 0; nt < 8; nt++) {
                int kcol = k0 + nt * 8 + 2 * tq;
                bool mk[4];
                if (mask_esize == 4) {
                    const unsigned int* mm = (const unsigned int*)mask;
                    mk[0] = mm[mask_base + (size_t)qg0 * SEQ + kcol] != 0;
                    mk[1] = mm[mask_base + (size_t)qg0 * SEQ + kcol + 1] != 0;
                    mk[2] = mm[mask_base + (size_t)qg1 * SEQ + kcol] != 0;
                    mk[3] = mm[mask_base + (size_t)qg1 * SEQ + kcol + 1] != 0;
                } else {
                    const unsigned char* mm = (const unsigned char*)mask;
                    mk[0] = mm[mask_base + (size_t)qg0 * SEQ + kcol] != 0;
                    mk[1] = mm[mask_base + (size_t)qg0 * SEQ + kcol + 1] != 0;
                    mk[2] = mm[mask_base + (size_t)qg1 * SEQ + kcol] != 0;
                    mk[3] = mm[mask_base + (size_t)qg1 * SEQ + kcol + 1] != 0;
                }
#pragma unroll
                for (int r = 0; r < 4; r++)
                    if (!mk[r]) s4[nt][r] = -1e9f;
            }
        }

        float mt0 = -1e30f, mt1 = -1e30f;
#pragma unroll
        for (int nt = 0; nt < 8; nt++) {
            mt0 = fmaxf(mt0, fmaxf(s4[nt][0], s4[nt][1]));
            mt1 = fmaxf(mt1, fmaxf(s4[nt][2], s4[nt][3]));
        }
        mt0 = fmaxf(mt0, __shfl_xor_sync(0xffffffff, mt0, 1));
        mt0 = fmaxf(mt0, __shfl_xor_sync(0xffffffff, mt0, 2));
        mt1 = fmaxf(mt1, __shfl_xor_sync(0xffffffff, mt1, 1));
        mt1 = fmaxf(mt1, __shfl_xor_sync(0xffffffff, mt1, 2));

        float mn0 = fmaxf(m0r, mt0), mn1 = fmaxf(m1r, mt1);
        float a0 = __expf(m0r - mn0), a1 = __expf(m1r - mn1);
        m0r = mn0; m1r = mn1;

        float lt0 = 0.0f, lt1 = 0.0f;
#pragma unroll
        for (int nt = 0; nt < 8; nt++) {
            s4[nt][0] = __expf(s4[nt][0] - mn0);
            s4[nt][1] = __expf(s4[nt][1] - mn0);
            s4[nt][2] = __expf(s4[nt][2] - mn1);
            s4[nt][3] = __expf(s4[nt][3] - mn1);
            lt0 += s4[nt][0] + s4[nt][1];
            lt1 += s4[nt][2] + s4[nt][3];
        }
        lt0 += __shfl_xor_sync(0xffffffff, lt0, 1);
        lt0 += __shfl_xor_sync(0xffffffff, lt0, 2);
        lt1 += __shfl_xor_sync(0xffffffff, lt1, 1);
        lt1 += __shfl_xor_sync(0xffffffff, lt1, 2);
        l0r = l0r * a0 + lt0;
        l1r = l1r * a1 + lt1;

#pragma unroll
        for (int nt = 0; nt < 8; nt++) {
            o[nt][0] *= a0; o[nt][1] *= a0;
            o[nt][2] *= a1; o[nt][3] *= a1;
        }

#pragma unroll
        for (int kb = 0; kb < 8; kb++) {
            uint32_t pa0 = to_tf32(s4[kb][0]);
            uint32_t pa1 = to_tf32(s4[kb][2]);
            uint32_t pa2 = to_tf32(s4[kb][1]);
            uint32_t pa3 = to_tf32(s4[kb][3]);
            const int vr0 = (kb * 8 + 2 * tq) * 76;
            const int vr1 = (kb * 8 + 2 * tq + 1) * 76;
#pragma unroll
            for (int nt = 0; nt < 8; nt++) {
                const int d = nt * 8 + g;
                mma_tf32(o[nt], pa0, pa1, pa2, pa3,
                         Vtf_s[vr0 + d], Vtf_s[vr1 + d]);
            }
        }
        __syncthreads();
    }

    const float inv0 = 1.0f / l0r, inv1 = 1.0f / l1r;
    const size_t row0 = rbase + q0 + wq + g;
    const size_t row1 = row0 + 8;
#pragma unroll
    for (int nt = 0; nt < 8; nt++) {
        const int col = hoff + nt * 8 + 2 * tq;
        *reinterpret_cast<uint2*>(&atttf[row0 * EMB + col]) =
            make_uint2(to_tf32(o[nt][0] * inv0), to_tf32(o[nt][1] * inv0));
        *reinterpret_cast<uint2*>(&atttf[row1 * EMB + col]) =
            make_uint2(to_tf32(o[nt][2] * inv1), to_tf32(o[nt][3] * inv1));
    }
}

// ============================================================================
extern "C" void kernel_launch(void* const* d_in, const int* in_sizes, int n_in,
                              void* d_out, int out_size) {
    const float* x      = (const float*)d_in[0];
    const void*  mask   = d_in[1];
    const float* W_pre  = (const float*)d_in[2];
    const float* b_pre  = (const float*)d_in[3];
    const float* W_proj = (const float*)d_in[4];
    const float* b_proj = (const float*)d_in[5];
    float* out = (float*)d_out;

    uint32_t *qtf, *ktf, *vtf, *xtf, *atttf, *wpretf, *wprojtf;
    cudaGetSymbolAddress((void**)&qtf, g_qtf);
    cudaGetSymbolAddress((void**)&ktf, g_ktf);
    cudaGetSymbolAddress((void**)&vtf, g_vtf);
    cudaGetSymbolAddress((void**)&xtf, g_xtf);
    cudaGetSymbolAddress((void**)&atttf, g_atttf);
    cudaGetSymbolAddress((void**)&wpretf, g_wpretf);
    cudaGetSymbolAddress((void**)&wprojtf, g_wprojtf);

    mask_scan_kernel<<<512, 256>>>((const uint4*)mask);
    cvt_all_kernel<<<2048, 256>>>((const float4*)x, (const float4*)W_pre,
                                  (const float4*)W_proj,
                                  (uint4*)xtf, (uint4*)wpretf, (uint4*)wprojtf);

    cudaFuncSetAttribute(gemm_tf_kernel<0>,
                         cudaFuncAttributeMaxDynamicSharedMemorySize, G5_BYTES);
    cudaFuncSetAttribute(gemm_tf_kernel<1>,
                         cudaFuncAttributeMaxDynamicSharedMemorySize, G5_BYTES);
    cudaFuncSetAttribute(attn_mma_kernel,
                         cudaFuncAttributeMaxDynamicSharedMemorySize, AT4_BYTES);

    // 1) QKV GEMM -> attention-ready operands
    {
        dim3 grid(QKVN / 128, ROWS / 128);
        gemm_tf_kernel<1><<<grid, 256, G5_BYTES>>>(
            xtf, wpretf, b_pre, nullptr, qtf, ktf, vtf, ROWS, QKVN, EMB);
    }
    // 2) Attention (R12 winner)
    {
        dim3 grid(SEQ / 128, HEADS, BATCH);
        attn_mma_kernel<<<grid, 256, AT4_BYTES>>>(qtf, ktf, vtf, mask, atttf);
    }
    // 3) Projection GEMM
    {
        dim3 grid(EMB / 128, ROWS / 128);
        gemm_tf_kernel<0><<<grid, 256, G5_BYTES>>>(
            atttf, wprojtf, b_proj, out, nullptr, nullptr, nullptr,
            ROWS, EMB, EMB);
    }
}